// round 4
// baseline (speedup 1.0000x reference)
#include <cuda_runtime.h>
#include <cuda_bf16.h>
#include <math.h>
#include <stdint.h>

#define Gn   256      // graphs
#define Nn   512      // nodes per graph
#define En   16384    // edges per graph
#define Hh   256      // hidden
#define FIN  4
#define TASKS 512     // 256 home + 256 away

// ---------------- scratch (device globals; no allocation) ----------------
__device__ float g_X[2][(size_t)TASKS * Nn * Hh];   // ping-pong
__device__ float g_deg[TASKS * Nn];
__device__ float g_dinv[TASKS * Nn];
__device__ float g_selfnorm[TASKS * Nn];
__device__ int   g_cnt[TASKS * Nn];
__device__ int   g_cnt2[TASKS * Nn];
__device__ int   g_rowptr[TASKS * (Nn + 1)];
__device__ int2  g_edge[(size_t)TASKS * En];        // (src, f32-bits of norm)
__device__ float g_pool[TASKS * Hh];
__device__ float g_Wt[4 * Hh * Hh];                 // tf32-rounded weights, [l][k][n]

__device__ __forceinline__ float totf32(float x) {
    uint32_t o;
    asm("cvt.rna.tf32.f32 %0, %1;" : "=r"(o) : "f"(x));
    return __uint_as_float(o);
}
__device__ __forceinline__ uint32_t smem_u32(const void* p) {
    uint32_t a;
    asm("{ .reg .u64 t; cvta.to.shared.u64 t, %1; cvt.u32.u64 %0, t; }" : "=r"(a) : "l"(p));
    return a;
}
__device__ __forceinline__ void cpasync16(uint32_t dst, const void* src) {
    asm volatile("cp.async.cg.shared.global [%0], [%1], 16;" :: "r"(dst), "l"(src) : "memory");
}
__device__ __forceinline__ void mma_tf32(float* c, const uint32_t* a, const uint32_t* b) {
    asm volatile(
        "mma.sync.aligned.m16n8k8.row.col.f32.tf32.tf32.f32 "
        "{%0,%1,%2,%3}, {%4,%5,%6,%7}, {%8,%9}, {%0,%1,%2,%3};"
        : "+f"(c[0]), "+f"(c[1]), "+f"(c[2]), "+f"(c[3])
        : "r"(a[0]), "r"(a[1]), "r"(a[2]), "r"(a[3]), "r"(b[0]), "r"(b[1]));
}

// ---------------- prep: degree / CSR build ----------------
__global__ void prep_init() {
    int i = blockIdx.x * Nn + threadIdx.x;
    g_deg[i] = 1.0f;
    g_cnt[i] = 0;
    g_cnt2[i] = 0;
    if (i < TASKS * Hh) g_pool[i] = 0.0f;
}

__global__ void prep_count(const int* __restrict__ hei, const int* __restrict__ aei,
                           const float* __restrict__ hew, const float* __restrict__ aew) {
    int task = blockIdx.x;
    int e = blockIdx.y * 256 + threadIdx.x;
    const int*   ei = (task < Gn) ? hei + (size_t)task * 2 * En : aei + (size_t)(task - Gn) * 2 * En;
    const float* ew = (task < Gn) ? hew + (size_t)task * En     : aew + (size_t)(task - Gn) * En;
    int t = ei[En + e];
    float w = ew[e];
    atomicAdd(&g_deg[task * Nn + t], w);
    atomicAdd(&g_cnt[task * Nn + t], 1);
}

__global__ void prep_scan() {
    __shared__ int s[Nn];
    int task = blockIdx.x, t = threadIdx.x;
    s[t] = g_cnt[task * Nn + t];
    __syncthreads();
    for (int off = 1; off < Nn; off <<= 1) {
        int v = (t >= off) ? s[t - off] : 0;
        __syncthreads();
        s[t] += v;
        __syncthreads();
    }
    g_rowptr[task * (Nn + 1) + t + 1] = s[t];
    if (t == 0) g_rowptr[task * (Nn + 1)] = 0;
    float d  = g_deg[task * Nn + t];
    float di = rsqrtf(d);
    g_dinv[task * Nn + t] = di;
    g_selfnorm[task * Nn + t] = di * di;
}

__global__ void prep_scatter(const int* __restrict__ hei, const int* __restrict__ aei,
                             const float* __restrict__ hew, const float* __restrict__ aew) {
    int task = blockIdx.x;
    int e = blockIdx.y * 256 + threadIdx.x;
    const int*   ei = (task < Gn) ? hei + (size_t)task * 2 * En : aei + (size_t)(task - Gn) * 2 * En;
    const float* ew = (task < Gn) ? hew + (size_t)task * En     : aew + (size_t)(task - Gn) * En;
    int s = ei[e];
    int t = ei[En + e];
    float w = ew[e];
    float norm = g_dinv[task * Nn + s] * w * g_dinv[task * Nn + t];
    int pos = g_rowptr[task * (Nn + 1) + t] + atomicAdd(&g_cnt2[task * Nn + t], 1);
    g_edge[(size_t)task * En + pos] = make_int2(s, __float_as_int(norm));
}

// ---------------- weight tf32 round ----------------
__global__ void wt_prep(const float* __restrict__ Wh) {
    size_t i = (size_t)blockIdx.x * 256 + threadIdx.x;
    g_Wt[i] = totf32(Wh[i]);
}

// ---------------- layer 0 GEMM: T = X[512,4] @ W0[4,256] ----------------
__global__ void gemm0(const float* __restrict__ hx, const float* __restrict__ ax,
                      const float* __restrict__ W0) {
    int task = blockIdx.x;
    int n0 = blockIdx.y * 8;
    int h = threadIdx.x;
    const float* x = (task < Gn) ? hx + (size_t)task * Nn * FIN
                                 : ax + (size_t)(task - Gn) * Nn * FIN;
    float w0 = W0[h], w1 = W0[Hh + h], w2 = W0[2 * Hh + h], w3 = W0[3 * Hh + h];
    float* T = &g_X[1][(size_t)task * Nn * Hh];
#pragma unroll
    for (int i = 0; i < 8; i++) {
        int n = n0 + i;
        float4 xv = *(const float4*)(x + n * 4);
        T[n * Hh + h] = xv.x * w0 + xv.y * w1 + xv.z * w2 + xv.w * w3;
    }
}

// ---------------- tf32 mma.sync GEMM v2: cp.async double-buffered ----------------
// CTA 128x128, 128 threads = 4 warps of 64x64. grid (2, 4, 512).
#define AS_S 36
#define BS_S 132
#define ASZ (128 * AS_S)
#define BSZ (32 * BS_S)
static const uint32_t GEMM_SMEM = 2 * (ASZ + BSZ) * 4;   // 70656 B

__global__ __launch_bounds__(128) void gemm_mma(int layer) {
    extern __shared__ float smp[];
    float* Asm = smp;                 // [2][ASZ]
    float* Bsm = smp + 2 * ASZ;       // [2][BSZ]

    const int task = blockIdx.z;
    const int bm = blockIdx.y * 128;
    const int bn = blockIdx.x * 128;
    const float* A = &g_X[0][(size_t)task * Nn * Hh + (size_t)bm * Hh];   // tf32-rounded
    float*       C = &g_X[1][(size_t)task * Nn * Hh + (size_t)bm * Hh + bn];
    const float* W = g_Wt + (size_t)layer * Hh * Hh + bn;

    const int tid  = threadIdx.x;
    const int lane = tid & 31;
    const int wid  = tid >> 5;
    const int m_off = (wid & 1) * 64;
    const int n_off = (wid >> 1) * 64;
    const int gid = lane >> 2;
    const int tig = lane & 3;

    const uint32_t sA = smem_u32(Asm);
    const uint32_t sB = smem_u32(Bsm);

    float acc[4][8][4];
#pragma unroll
    for (int mi = 0; mi < 4; mi++)
#pragma unroll
        for (int ni = 0; ni < 8; ni++)
#pragma unroll
            for (int q = 0; q < 4; q++) acc[mi][ni][q] = 0.f;

#define ISSUE(kb)                                                              \
    {                                                                          \
        int _buf = (kb) & 1;                                                   \
        uint32_t _da = sA + _buf * ASZ * 4;                                    \
        uint32_t _db = sB + _buf * BSZ * 4;                                    \
        _Pragma("unroll")                                                      \
        for (int it = 0; it < 8; it++) {                                       \
            int id = tid + it * 128;                                           \
            int r = id >> 3, q = id & 7;                                       \
            cpasync16(_da + (r * AS_S + q * 4) * 4,                            \
                      A + (size_t)r * Hh + (kb) * 32 + q * 4);                 \
        }                                                                      \
        _Pragma("unroll")                                                      \
        for (int it = 0; it < 8; it++) {                                       \
            int id = tid + it * 128;                                           \
            int r = id >> 5, q = id & 31;                                      \
            cpasync16(_db + (r * BS_S + q * 4) * 4,                            \
                      W + (size_t)((kb) * 32 + r) * Hh + q * 4);               \
        }                                                                      \
        asm volatile("cp.async.commit_group;" ::: "memory");                   \
    }

    ISSUE(0);
    ISSUE(1);

    for (int kb = 0; kb < 8; kb++) {
        if (kb == 7) asm volatile("cp.async.wait_group 0;" ::: "memory");
        else         asm volatile("cp.async.wait_group 1;" ::: "memory");
        __syncthreads();

        const float* as = Asm + (kb & 1) * ASZ;
        const float* bs = Bsm + (kb & 1) * BSZ;

#pragma unroll
        for (int ks = 0; ks < 4; ks++) {
            const int k = ks * 8;
            uint32_t af[4][4], bf[8][2];
#pragma unroll
            for (int mi = 0; mi < 4; mi++) {
                int m = m_off + mi * 16 + gid;
                af[mi][0] = __float_as_uint(as[m * AS_S + k + tig]);
                af[mi][1] = __float_as_uint(as[(m + 8) * AS_S + k + tig]);
                af[mi][2] = __float_as_uint(as[m * AS_S + k + tig + 4]);
                af[mi][3] = __float_as_uint(as[(m + 8) * AS_S + k + tig + 4]);
            }
#pragma unroll
            for (int ni = 0; ni < 8; ni++) {
                int n = n_off + ni * 8 + gid;
                bf[ni][0] = __float_as_uint(bs[(k + tig) * BS_S + n]);
                bf[ni][1] = __float_as_uint(bs[(k + tig + 4) * BS_S + n]);
            }
#pragma unroll
            for (int mi = 0; mi < 4; mi++)
#pragma unroll
                for (int ni = 0; ni < 8; ni++)
                    mma_tf32(acc[mi][ni], af[mi], bf[ni]);
        }
        __syncthreads();
        if (kb + 2 < 8) ISSUE(kb + 2);
    }

#pragma unroll
    for (int mi = 0; mi < 4; mi++) {
        int r0 = m_off + mi * 16 + gid;
#pragma unroll
        for (int ni = 0; ni < 8; ni++) {
            int cl = n_off + ni * 8 + tig * 2;
            *(float2*)(C + (size_t)r0 * Hh + cl)       = make_float2(acc[mi][ni][0], acc[mi][ni][1]);
            *(float2*)(C + (size_t)(r0 + 8) * Hh + cl) = make_float2(acc[mi][ni][2], acc[mi][ni][3]);
        }
    }
#undef ISSUE
}

// ---------------- aggregation v2: broadcast LDG edges, tf32-rounded output ----------------
// grid (4 channel-slices, TASKS), block 512 (16 warps), 128KB dyn smem.
__global__ __launch_bounds__(512) void aggregate(const float* __restrict__ bias, int do_pool) {
    extern __shared__ float sh[];   // [Nn][64]
    int task = blockIdx.y;
    int c0 = blockIdx.x * 64;
    const float* T = &g_X[1][(size_t)task * Nn * Hh];
    float*    Hout = &g_X[0][(size_t)task * Nn * Hh];

    for (int i = threadIdx.x; i < Nn * 16; i += blockDim.x) {
        int n = i >> 4, q = i & 15;
        ((float4*)sh)[n * 16 + q] = *(const float4*)(T + (size_t)n * Hh + c0 + q * 4);
    }
    __syncthreads();

    int lane = threadIdx.x & 31, warp = threadIdx.x >> 5;
    float b0 = bias[c0 + lane], b1 = bias[c0 + 32 + lane];
    const int*  rp = g_rowptr + task * (Nn + 1);
    const int2* ed = g_edge + (size_t)task * En;

    float p0 = 0.f, p1 = 0.f;

    for (int t = warp; t < Nn; t += 16) {
        float a0 = b0, a1 = b1;
        int rs = rp[t], re = rp[t + 1];
        int e = rs;
        for (; e + 4 <= re; e += 4) {
            int2 e0 = ed[e], e1 = ed[e + 1], e2 = ed[e + 2], e3 = ed[e + 3];
            float v0 = __int_as_float(e0.y), v1 = __int_as_float(e1.y);
            float v2 = __int_as_float(e2.y), v3 = __int_as_float(e3.y);
            a0 += v0 * sh[e0.x * 64 + lane];      a1 += v0 * sh[e0.x * 64 + 32 + lane];
            a0 += v1 * sh[e1.x * 64 + lane];      a1 += v1 * sh[e1.x * 64 + 32 + lane];
            a0 += v2 * sh[e2.x * 64 + lane];      a1 += v2 * sh[e2.x * 64 + 32 + lane];
            a0 += v3 * sh[e3.x * 64 + lane];      a1 += v3 * sh[e3.x * 64 + 32 + lane];
        }
        for (; e < re; e++) {
            int2 ev = ed[e];
            float v = __int_as_float(ev.y);
            a0 += v * sh[ev.x * 64 + lane];
            a1 += v * sh[ev.x * 64 + 32 + lane];
        }
        float sn = g_selfnorm[task * Nn + t];
        a0 += sn * sh[t * 64 + lane];
        a1 += sn * sh[t * 64 + 32 + lane];
        a0 = fmaxf(a0, 0.f); a1 = fmaxf(a1, 0.f);
        p0 += a0; p1 += a1;
        // store tf32-rounded so gemm_mma can consume raw (A operand pre-rounded)
        Hout[(size_t)t * Hh + c0 + lane]      = totf32(a0);
        Hout[(size_t)t * Hh + c0 + 32 + lane] = totf32(a1);
    }

    if (do_pool) {
        atomicAdd(&g_pool[task * Hh + c0 + lane],      p0);
        atomicAdd(&g_pool[task * Hh + c0 + 32 + lane], p1);
    }
}

// ---------------- FC head (pool scale folded in) ----------------
__global__ void fck(const float* __restrict__ hfeat, const float* __restrict__ afeat,
                    const float* __restrict__ fcW, const float* __restrict__ fcb,
                    float* __restrict__ out) {
    int g = blockIdx.x;
    int c = threadIdx.x >> 5;
    int lane = threadIdx.x & 31;
    const float ps = 1.0f / Nn;
    float acc = 0.f;
    for (int i = lane; i < 2 * (Hh + 6); i += 32) {
        float xv;
        if      (i < 256) xv = g_pool[g * Hh + i] * ps;
        else if (i < 262) xv = hfeat[g * 6 + (i - 256)];
        else if (i < 518) xv = g_pool[(Gn + g) * Hh + (i - 262)] * ps;
        else              xv = afeat[g * 6 + (i - 518)];
        acc += xv * fcW[i * 3 + c];
    }
#pragma unroll
    for (int o = 16; o; o >>= 1) acc += __shfl_down_sync(0xffffffff, acc, o);
    if (lane == 0) out[g * 3 + c] = acc + fcb[c];
}

// ---------------- launch ----------------
extern "C" void kernel_launch(void* const* d_in, const int* in_sizes, int n_in,
                              void* d_out, int out_size) {
    const float* home_x = (const float*)d_in[0];
    const float* away_x = (const float*)d_in[1];
    const int*   hei    = (const int*)d_in[2];
    const int*   aei    = (const int*)d_in[3];
    const float* hew    = (const float*)d_in[4];
    const float* aew    = (const float*)d_in[5];
    const float* hfeat  = (const float*)d_in[6];
    const float* afeat  = (const float*)d_in[7];
    const float* W0     = (const float*)d_in[8];
    const float* Wh     = (const float*)d_in[9];
    const float* bs     = (const float*)d_in[10];
    const float* fcW    = (const float*)d_in[11];
    const float* fcb    = (const float*)d_in[12];
    float* out = (float*)d_out;

    cudaFuncSetAttribute(aggregate, cudaFuncAttributeMaxDynamicSharedMemorySize, 131072);
    cudaFuncSetAttribute(gemm_mma, cudaFuncAttributeMaxDynamicSharedMemorySize, GEMM_SMEM);

    // build normalized adjacency CSR + tf32 weights (shared by all layers)
    wt_prep<<<4 * Hh * Hh / 256, 256>>>(Wh);
    prep_init<<<TASKS, Nn>>>();
    prep_count<<<dim3(TASKS, En / 256), 256>>>(hei, aei, hew, aew);
    prep_scan<<<TASKS, Nn>>>();
    prep_scatter<<<dim3(TASKS, En / 256), 256>>>(hei, aei, hew, aew);

    // layer 0
    gemm0<<<dim3(TASKS, Nn / 8), Hh>>>(home_x, away_x, W0);
    aggregate<<<dim3(4, TASKS), 512, 131072>>>(bs, 0);

    // layers 1..4 on tensor cores (mma.sync tf32, cp.async pipelined)
    for (int l = 1; l < 5; l++) {
        gemm_mma<<<dim3(2, 4, TASKS), 128, GEMM_SMEM>>>(l - 1);
        aggregate<<<dim3(4, TASKS), 512, 131072>>>(bs + l * Hh, l == 4 ? 1 : 0);
    }

    // head
    fck<<<Gn, 96>>>(hfeat, afeat, fcW, fcb, out);
}

// round 5
// speedup vs baseline: 1.3172x; 1.3172x over previous
#include <cuda_runtime.h>
#include <cuda_bf16.h>
#include <math.h>
#include <stdint.h>

#define Gn   256      // graphs
#define Nn   512      // nodes per graph
#define En   16384    // edges per graph
#define Hh   256      // hidden
#define FIN  4
#define TASKS 512     // 256 home + 256 away
#define HP   128      // Hh/2 pairs

// ---------------- scratch (device globals; no allocation) ----------------
__device__ __nv_bfloat16 g_A[(size_t)TASKS * Nn * Hh];   // aggregate out = GEMM A operand
__device__ uint32_t      g_C[(size_t)TASKS * Nn * HP];   // GEMM out (bf16 pairs) = aggregate in
__device__ float g_deg[TASKS * Nn];
__device__ float g_dinv[TASKS * Nn];
__device__ float g_selfnorm[TASKS * Nn];
__device__ int   g_cnt[TASKS * Nn];
__device__ int   g_cnt2[TASKS * Nn];
__device__ int   g_rowptr[TASKS * (Nn + 1)];
__device__ int2  g_edge[(size_t)TASKS * En];             // (src, f32-bits of norm)
__device__ float g_pool[TASKS * Hh];
__device__ __nv_bfloat16 g_Wtb[4 * Hh * Hh];             // bf16 weights, [l][n][k] (transposed)

__device__ __forceinline__ uint32_t smem_u32(const void* p) {
    uint32_t a;
    asm("{ .reg .u64 t; cvta.to.shared.u64 t, %1; cvt.u32.u64 %0, t; }" : "=r"(a) : "l"(p));
    return a;
}
__device__ __forceinline__ void cpasync16(uint32_t dst, const void* src) {
    asm volatile("cp.async.cg.shared.global [%0], [%1], 16;" :: "r"(dst), "l"(src) : "memory");
}
__device__ __forceinline__ void ldsm_x4(uint32_t& r0, uint32_t& r1, uint32_t& r2, uint32_t& r3,
                                        uint32_t addr) {
    asm volatile("ldmatrix.sync.aligned.m8n8.x4.shared.b16 {%0,%1,%2,%3}, [%4];"
                 : "=r"(r0), "=r"(r1), "=r"(r2), "=r"(r3) : "r"(addr));
}
__device__ __forceinline__ void mma_bf16(float* c, const uint32_t* a, const uint32_t* b) {
    asm volatile(
        "mma.sync.aligned.m16n8k16.row.col.f32.bf16.bf16.f32 "
        "{%0,%1,%2,%3}, {%4,%5,%6,%7}, {%8,%9}, {%0,%1,%2,%3};"
        : "+f"(c[0]), "+f"(c[1]), "+f"(c[2]), "+f"(c[3])
        : "r"(a[0]), "r"(a[1]), "r"(a[2]), "r"(a[3]), "r"(b[0]), "r"(b[1]));
}

// ---------------- prep: degree / CSR build ----------------
__global__ void prep_init() {
    int i = blockIdx.x * Nn + threadIdx.x;
    g_deg[i] = 1.0f;
    g_cnt[i] = 0;
    g_cnt2[i] = 0;
    if (i < TASKS * Hh) g_pool[i] = 0.0f;
}

__global__ void prep_count(const int* __restrict__ hei, const int* __restrict__ aei,
                           const float* __restrict__ hew, const float* __restrict__ aew) {
    int task = blockIdx.x;
    int e = blockIdx.y * 256 + threadIdx.x;
    const int*   ei = (task < Gn) ? hei + (size_t)task * 2 * En : aei + (size_t)(task - Gn) * 2 * En;
    const float* ew = (task < Gn) ? hew + (size_t)task * En     : aew + (size_t)(task - Gn) * En;
    int t = ei[En + e];
    float w = ew[e];
    atomicAdd(&g_deg[task * Nn + t], w);
    atomicAdd(&g_cnt[task * Nn + t], 1);
}

__global__ void prep_scan() {
    __shared__ int s[Nn];
    int task = blockIdx.x, t = threadIdx.x;
    s[t] = g_cnt[task * Nn + t];
    __syncthreads();
    for (int off = 1; off < Nn; off <<= 1) {
        int v = (t >= off) ? s[t - off] : 0;
        __syncthreads();
        s[t] += v;
        __syncthreads();
    }
    g_rowptr[task * (Nn + 1) + t + 1] = s[t];
    if (t == 0) g_rowptr[task * (Nn + 1)] = 0;
    float d  = g_deg[task * Nn + t];
    float di = rsqrtf(d);
    g_dinv[task * Nn + t] = di;
    g_selfnorm[task * Nn + t] = di * di;
}

__global__ void prep_scatter(const int* __restrict__ hei, const int* __restrict__ aei,
                             const float* __restrict__ hew, const float* __restrict__ aew) {
    int task = blockIdx.x;
    int e = blockIdx.y * 256 + threadIdx.x;
    const int*   ei = (task < Gn) ? hei + (size_t)task * 2 * En : aei + (size_t)(task - Gn) * 2 * En;
    const float* ew = (task < Gn) ? hew + (size_t)task * En     : aew + (size_t)(task - Gn) * En;
    int s = ei[e];
    int t = ei[En + e];
    float w = ew[e];
    float norm = g_dinv[task * Nn + s] * w * g_dinv[task * Nn + t];
    int pos = g_rowptr[task * (Nn + 1) + t] + atomicAdd(&g_cnt2[task * Nn + t], 1);
    g_edge[(size_t)task * En + pos] = make_int2(s, __float_as_int(norm));
}

// ---------------- weight prep: Wtb[l][n][k] = bf16(Wh[l][k][n]) ----------------
__global__ void wt_prep(const float* __restrict__ Wh) {
    int l = blockIdx.y, n = blockIdx.x, k = threadIdx.x;
    g_Wtb[(size_t)l * Hh * Hh + (size_t)n * Hh + k] =
        __float2bfloat16(Wh[(size_t)l * Hh * Hh + (size_t)k * Hh + n]);
}

// ---------------- layer 0 GEMM: C = X[512,4] @ W0[4,256], bf16-pair out ----------------
__global__ void gemm0(const float* __restrict__ hx, const float* __restrict__ ax,
                      const float* __restrict__ W0) {
    int task = blockIdx.x;
    int n0 = blockIdx.y * 8;
    int h = threadIdx.x;     // pair index 0..127
    const float* x = (task < Gn) ? hx + (size_t)task * Nn * FIN
                                 : ax + (size_t)(task - Gn) * Nn * FIN;
    float wa0 = W0[2 * h],            wb0 = W0[2 * h + 1];
    float wa1 = W0[Hh + 2 * h],       wb1 = W0[Hh + 2 * h + 1];
    float wa2 = W0[2 * Hh + 2 * h],   wb2 = W0[2 * Hh + 2 * h + 1];
    float wa3 = W0[3 * Hh + 2 * h],   wb3 = W0[3 * Hh + 2 * h + 1];
    uint32_t* C = g_C + (size_t)task * Nn * HP;
#pragma unroll
    for (int i = 0; i < 8; i++) {
        int n = n0 + i;
        float4 xv = *(const float4*)(x + n * 4);
        float c0 = xv.x * wa0 + xv.y * wa1 + xv.z * wa2 + xv.w * wa3;
        float c1 = xv.x * wb0 + xv.y * wb1 + xv.z * wb2 + xv.w * wb3;
        __nv_bfloat162 p = __float22bfloat162_rn(make_float2(c0, c1));
        C[n * HP + h] = *reinterpret_cast<uint32_t*>(&p);
    }
}

// ---------------- bf16 mma.sync GEMM: C[128,128] = A[128,256] @ W^T ----------------
// CTA 128x128 tile, 128 threads = 4 warps of 64x64. grid (2, 4, 512).
// smem: A/B chunks [128 rows][32 k] bf16, row stride 40 bf16 (80 B, ldmatrix conflict-free).
#define AST 40
#define CHB (128 * AST * 2)    // 10240 B per chunk buffer

__global__ __launch_bounds__(128) void gemm_mma(int layer) {
    __shared__ __align__(128) char smg[4 * CHB];   // [A0][A1][B0][B1]

    const int task = blockIdx.z;
    const int bm = blockIdx.y * 128;
    const int bn = blockIdx.x * 128;
    const __nv_bfloat16* A = g_A + (size_t)task * Nn * Hh + (size_t)bm * Hh;
    uint32_t*            C = g_C + (size_t)task * Nn * HP + (size_t)bm * HP + bn / 2;
    const __nv_bfloat16* W = g_Wtb + (size_t)layer * Hh * Hh + (size_t)bn * Hh;

    const int tid  = threadIdx.x;
    const int lane = tid & 31;
    const int wid  = tid >> 5;
    const int m_off = (wid & 1) * 64;
    const int n_off = (wid >> 1) * 64;
    const int gid = lane >> 2;
    const int tig = lane & 3;

    const uint32_t sm0 = smem_u32(smg);

    // ldmatrix lane address components
    const int a_row = (lane & 15);
    const int a_kc  = (lane >> 4) * 8;
    const int b_row = (lane & 7) + (lane >> 4) * 8;
    const int b_kc  = ((lane >> 3) & 1) * 8;

    float acc[4][8][4];
#pragma unroll
    for (int mi = 0; mi < 4; mi++)
#pragma unroll
        for (int ni = 0; ni < 8; ni++)
#pragma unroll
            for (int q = 0; q < 4; q++) acc[mi][ni][q] = 0.f;

#define ISSUE(kb)                                                               \
    {                                                                           \
        int _buf = (kb) & 1;                                                    \
        uint32_t _da = sm0 + _buf * CHB;                                        \
        uint32_t _db = sm0 + (2 + _buf) * CHB;                                  \
        _Pragma("unroll")                                                       \
        for (int it = 0; it < 4; it++) {                                        \
            int id = tid + it * 128;                                            \
            int r = id >> 2, q = id & 3;                                        \
            cpasync16(_da + r * (AST * 2) + q * 16,                             \
                      A + (size_t)r * Hh + (kb) * 32 + q * 8);                  \
        }                                                                       \
        _Pragma("unroll")                                                       \
        for (int it = 0; it < 4; it++) {                                        \
            int id = tid + it * 128;                                            \
            int r = id >> 2, q = id & 3;                                        \
            cpasync16(_db + r * (AST * 2) + q * 16,                             \
                      W + (size_t)r * Hh + (kb) * 32 + q * 8);                  \
        }                                                                       \
        asm volatile("cp.async.commit_group;" ::: "memory");                    \
    }

    ISSUE(0);
    ISSUE(1);

    for (int kb = 0; kb < 8; kb++) {
        if (kb == 7) asm volatile("cp.async.wait_group 0;" ::: "memory");
        else         asm volatile("cp.async.wait_group 1;" ::: "memory");
        __syncthreads();

        uint32_t aA = sm0 + (kb & 1) * CHB;
        uint32_t aB = sm0 + (2 + (kb & 1)) * CHB;

#pragma unroll
        for (int ks = 0; ks < 2; ks++) {
            const int k0 = ks * 16;
            uint32_t af[4][4], bf[8][2];
#pragma unroll
            for (int mi = 0; mi < 4; mi++) {
                uint32_t ad = aA + (m_off + mi * 16 + a_row) * (AST * 2) + (k0 + a_kc) * 2;
                ldsm_x4(af[mi][0], af[mi][1], af[mi][2], af[mi][3], ad);
            }
#pragma unroll
            for (int nip = 0; nip < 4; nip++) {
                uint32_t bd = aB + (n_off + nip * 16 + b_row) * (AST * 2) + (k0 + b_kc) * 2;
                ldsm_x4(bf[nip * 2][0], bf[nip * 2][1], bf[nip * 2 + 1][0], bf[nip * 2 + 1][1], bd);
            }
#pragma unroll
            for (int mi = 0; mi < 4; mi++)
#pragma unroll
                for (int ni = 0; ni < 8; ni++)
                    mma_bf16(acc[mi][ni], af[mi], bf[ni]);
        }
        __syncthreads();
        if (kb + 2 < 8) ISSUE(kb + 2);
    }

    // epilogue: pack adjacent cols (n, n+1) -> bf16x2 pair
#pragma unroll
    for (int mi = 0; mi < 4; mi++) {
        int r0 = m_off + mi * 16 + gid;
#pragma unroll
        for (int ni = 0; ni < 8; ni++) {
            int pi = n_off / 2 + ni * 4 + tig;
            __nv_bfloat162 p0 = __float22bfloat162_rn(make_float2(acc[mi][ni][0], acc[mi][ni][1]));
            __nv_bfloat162 p1 = __float22bfloat162_rn(make_float2(acc[mi][ni][2], acc[mi][ni][3]));
            C[(size_t)r0 * HP + pi]       = *reinterpret_cast<uint32_t*>(&p0);
            C[(size_t)(r0 + 8) * HP + pi] = *reinterpret_cast<uint32_t*>(&p1);
        }
    }
#undef ISSUE
}

// ---------------- aggregation: bf16-pair table, 1 LDS per edge ----------------
// grid (4 pair-slices, TASKS), block 256 (8 warps), 64KB dyn smem -> 3 CTAs/SM.
__global__ __launch_bounds__(256) void aggregate(const float* __restrict__ bias, int do_pool) {
    extern __shared__ uint32_t sh2[];   // [Nn][32 pairs]
    int task = blockIdx.y;
    int p0 = blockIdx.x * 32;           // pair offset
    const uint32_t* C = g_C + (size_t)task * Nn * HP;
    __nv_bfloat162* Hout = reinterpret_cast<__nv_bfloat162*>(g_A) + (size_t)task * Nn * HP;

    // stage [512 x 32] pair slice (pure copy, uint4)
    for (int i = threadIdx.x; i < Nn * 8; i += blockDim.x) {
        int n = i >> 3, q = i & 7;
        *(uint4*)&sh2[n * 32 + q * 4] = *(const uint4*)(C + (size_t)n * HP + p0 + q * 4);
    }
    __syncthreads();

    int lane = threadIdx.x & 31, warp = threadIdx.x >> 5;
    float b0 = bias[2 * (p0 + lane)], b1 = bias[2 * (p0 + lane) + 1];
    const int*  rp = g_rowptr + task * (Nn + 1);
    const int2* ed = g_edge + (size_t)task * En;

    float q0 = 0.f, q1 = 0.f;   // pool partials

    for (int t = warp; t < Nn; t += 8) {
        float a0 = b0, a1 = b1;
        int rs = rp[t], re = rp[t + 1];
        int e = rs;
        for (; e + 4 <= re; e += 4) {
            int2 e0 = ed[e], e1 = ed[e + 1], e2 = ed[e + 2], e3 = ed[e + 3];
            uint32_t u0 = sh2[e0.x * 32 + lane], u1 = sh2[e1.x * 32 + lane];
            uint32_t u2 = sh2[e2.x * 32 + lane], u3 = sh2[e3.x * 32 + lane];
            float2 h0 = __bfloat1622float2(*reinterpret_cast<__nv_bfloat162*>(&u0));
            float2 h1 = __bfloat1622float2(*reinterpret_cast<__nv_bfloat162*>(&u1));
            float2 h2 = __bfloat1622float2(*reinterpret_cast<__nv_bfloat162*>(&u2));
            float2 h3 = __bfloat1622float2(*reinterpret_cast<__nv_bfloat162*>(&u3));
            float v0 = __int_as_float(e0.y), v1 = __int_as_float(e1.y);
            float v2 = __int_as_float(e2.y), v3 = __int_as_float(e3.y);
            a0 += v0 * h0.x + v1 * h1.x + v2 * h2.x + v3 * h3.x;
            a1 += v0 * h0.y + v1 * h1.y + v2 * h2.y + v3 * h3.y;
        }
        for (; e < re; e++) {
            int2 ev = ed[e];
            uint32_t u = sh2[ev.x * 32 + lane];
            float2 h = __bfloat1622float2(*reinterpret_cast<__nv_bfloat162*>(&u));
            float v = __int_as_float(ev.y);
            a0 += v * h.x;
            a1 += v * h.y;
        }
        float sn = g_selfnorm[task * Nn + t];
        uint32_t us = sh2[t * 32 + lane];
        float2 hs = __bfloat1622float2(*reinterpret_cast<__nv_bfloat162*>(&us));
        a0 += sn * hs.x;
        a1 += sn * hs.y;
        a0 = fmaxf(a0, 0.f); a1 = fmaxf(a1, 0.f);
        q0 += a0; q1 += a1;
        Hout[(size_t)t * HP + p0 + lane] = __float22bfloat162_rn(make_float2(a0, a1));
    }

    if (do_pool) {
        atomicAdd(&g_pool[task * Hh + 2 * (p0 + lane)],     q0);
        atomicAdd(&g_pool[task * Hh + 2 * (p0 + lane) + 1], q1);
    }
}

// ---------------- FC head (pool scale folded in) ----------------
__global__ void fck(const float* __restrict__ hfeat, const float* __restrict__ afeat,
                    const float* __restrict__ fcW, const float* __restrict__ fcb,
                    float* __restrict__ out) {
    int g = blockIdx.x;
    int c = threadIdx.x >> 5;
    int lane = threadIdx.x & 31;
    const float ps = 1.0f / Nn;
    float acc = 0.f;
    for (int i = lane; i < 2 * (Hh + 6); i += 32) {
        float xv;
        if      (i < 256) xv = g_pool[g * Hh + i] * ps;
        else if (i < 262) xv = hfeat[g * 6 + (i - 256)];
        else if (i < 518) xv = g_pool[(Gn + g) * Hh + (i - 262)] * ps;
        else              xv = afeat[g * 6 + (i - 518)];
        acc += xv * fcW[i * 3 + c];
    }
#pragma unroll
    for (int o = 16; o; o >>= 1) acc += __shfl_down_sync(0xffffffff, acc, o);
    if (lane == 0) out[g * 3 + c] = acc + fcb[c];
}

// ---------------- launch ----------------
extern "C" void kernel_launch(void* const* d_in, const int* in_sizes, int n_in,
                              void* d_out, int out_size) {
    const float* home_x = (const float*)d_in[0];
    const float* away_x = (const float*)d_in[1];
    const int*   hei    = (const int*)d_in[2];
    const int*   aei    = (const int*)d_in[3];
    const float* hew    = (const float*)d_in[4];
    const float* aew    = (const float*)d_in[5];
    const float* hfeat  = (const float*)d_in[6];
    const float* afeat  = (const float*)d_in[7];
    const float* W0     = (const float*)d_in[8];
    const float* Wh     = (const float*)d_in[9];
    const float* bs     = (const float*)d_in[10];
    const float* fcW    = (const float*)d_in[11];
    const float* fcb    = (const float*)d_in[12];
    float* out = (float*)d_out;

    cudaFuncSetAttribute(aggregate, cudaFuncAttributeMaxDynamicSharedMemorySize, 65536);

    // build normalized adjacency CSR + bf16 transposed weights (shared by all layers)
    wt_prep<<<dim3(Hh, 4), Hh>>>(Wh);
    prep_init<<<TASKS, Nn>>>();
    prep_count<<<dim3(TASKS, En / 256), 256>>>(hei, aei, hew, aew);
    prep_scan<<<TASKS, Nn>>>();
    prep_scatter<<<dim3(TASKS, En / 256), 256>>>(hei, aei, hew, aew);

    // layer 0
    gemm0<<<dim3(TASKS, Nn / 8), 128>>>(home_x, away_x, W0);
    aggregate<<<dim3(4, TASKS), 256, 65536>>>(bs, 0);

    // layers 1..4 on tensor cores (mma.sync bf16)
    for (int l = 1; l < 5; l++) {
        gemm_mma<<<dim3(2, 4, TASKS), 128>>>(l - 1);
        aggregate<<<dim3(4, TASKS), 256, 65536>>>(bs + l * Hh, l == 4 ? 1 : 0);
    }

    // head
    fck<<<Gn, 96>>>(hfeat, afeat, fcW, fcb, out);
}